// round 10
// baseline (speedup 1.0000x reference)
#include <cuda_runtime.h>
#include <cuda_fp16.h>
#include <cstdint>

#define LL 1024
#define HH 2048
#define DDI 4096
#define NSS 16
#define RR 128

// ---------------- scratch ----------------
__device__ float  g_pg   [LL * 2 * DDI];   // [l,0:4096]=hs_pre, [l,4096:8192]=gate (fp32)
__device__ __half g_hsh  [LL * DDI];
__device__ __half g_tsh  [LL * RR];
__device__ float  g_dt   [LL * DDI];
__device__ float  g_tsbc [LL * 160];       // split-K accum: ts(128)|B(16)|C(16)
__device__ __half g_yh   [LL * DDI];
// half operand copies
__device__ __half g_xh   [LL * HH];
__device__ __half g_w12h [2 * DDI * HH];
__device__ __half g_wouth[HH * DDI];
__device__ __half g_wdtbch[160 * DDI];
__device__ __half g_wdtph [DDI * RR];

// ---------------- helpers ----------------
__device__ __forceinline__ uint32_t smem_u32(const void* p) {
    uint32_t a;
    asm("{ .reg .u64 t; cvta.to.shared.u64 t, %1; cvt.u32.u64 %0, t; }" : "=r"(a) : "l"(p));
    return a;
}
__device__ __forceinline__ void cp_async16(uint32_t dst, const void* src, bool pred) {
    int bytes = pred ? 16 : 0;
    asm volatile("cp.async.cg.shared.global [%0], [%1], 16, %2;" :: "r"(dst), "l"(src), "r"(bytes));
}
#define CP_COMMIT() asm volatile("cp.async.commit_group;" ::: "memory")
#define CP_WAIT2()  asm volatile("cp.async.wait_group 2;" ::: "memory")

__device__ __forceinline__ float softplusf(float x) {
    return (x > 20.f) ? x : log1pf(expf(x));
}
__device__ __forceinline__ void mma_f16(float* c, const uint32_t* a, const uint32_t* b) {
    asm volatile(
        "mma.sync.aligned.m16n8k16.row.col.f32.f16.f16.f32 "
        "{%0,%1,%2,%3}, {%4,%5,%6,%7}, {%8,%9}, {%0,%1,%2,%3};"
        : "+f"(c[0]), "+f"(c[1]), "+f"(c[2]), "+f"(c[3])
        : "r"(a[0]), "r"(a[1]), "r"(a[2]), "r"(a[3]), "r"(b[0]), "r"(b[1]));
}
#define LDSM_X4(r0, r1, r2, r3, addr) \
    asm volatile("ldmatrix.sync.aligned.m8n8.x4.shared.b16 {%0,%1,%2,%3}, [%4];" \
                 : "=r"(r0), "=r"(r1), "=r"(r2), "=r"(r3) : "r"(addr))

// ---------------- fp16 mma.sync GEMM: C[M,N] = A[M,K] . B[N,K]^T ----------------
// CTA tile 128x256, warp tile 64x64 (8 warps 2x4), BK=64 halfs, 4-stage cp.async
// (3 tiles in flight). EPI: 0 plain, 1 softplus(acc+bias[n]), 3 atomicAdd (split-K).
#define BM 128
#define BN 256
#define TROWS (BM + BN)                 // 384
#define SAPADH 72                        // halfs per row (144B)
#define STAGE_BYTES (TROWS * SAPADH * 2) // 55296
#define NSTAGE 4

template<int EPI>
__global__ __launch_bounds__(256, 1) void gemm_mma(
    const __half* __restrict__ A, const __half* __restrict__ B, float* __restrict__ C,
    const float* __restrict__ bias, int M, int N, int K, int ldc)
{
    extern __shared__ __half smem[];
    const int tid = threadIdx.x;
    const int wid = tid >> 5;
    const int lane = tid & 31;
    const int m0 = blockIdx.y * BM;
    const int n0 = blockIdx.x * BN;
    const int Ksplit = K / gridDim.z;
    const int kbase = blockIdx.z * Ksplit;
    const int KT = Ksplit >> 6;          // BK = 64

    const int wm = (wid >> 2) * 64;
    const int wn = (wid & 3) * 64;

    float acc[4][8][4];
#pragma unroll
    for (int i = 0; i < 4; i++)
#pragma unroll
        for (int j = 0; j < 8; j++)
#pragma unroll
            for (int r = 0; r < 4; r++) acc[i][j][r] = 0.f;

    const uint32_t smem_b = smem_u32(smem);

    uint32_t aoff[4], boff[4];
    {
        const int arow = lane & 15;
        const int acolh = (lane >> 4) * 8;
#pragma unroll
        for (int mt = 0; mt < 4; mt++)
            aoff[mt] = (uint32_t)(((wm + mt * 16 + arow) * SAPADH + acolh) * 2);
        const int bg = lane >> 3;
        const int br = lane & 7;
        const int nadd = (bg >> 1) * 8;
        const int khalf = (bg & 1) * 8;
#pragma unroll
        for (int p = 0; p < 4; p++)
            boff[p] = (uint32_t)(((BM + wn + 16 * p + nadd + br) * SAPADH + khalf) * 2);
    }

    auto load_tile = [&](int kt, int s) {
        const uint32_t a_s = smem_b + (uint32_t)(s * STAGE_BYTES);
        const uint32_t b_s = a_s + (uint32_t)(BM * SAPADH * 2);
        const int k0 = kbase + (kt << 6);
        const __half* Ab = A + (size_t)m0 * K + k0;
        const __half* Bb = B + (size_t)n0 * K + k0;
#pragma unroll
        for (int i = 0; i < 4; i++) {
            int idx = tid + i * 256;
            int row = idx >> 3;
            int ch = (idx & 7) << 3;
            cp_async16(a_s + (uint32_t)(row * SAPADH + ch) * 2u, Ab + (size_t)row * K + ch, true);
        }
#pragma unroll
        for (int i = 0; i < 8; i++) {
            int idx = tid + i * 256;
            int row = idx >> 3;
            int ch = (idx & 7) << 3;
            cp_async16(b_s + (uint32_t)(row * SAPADH + ch) * 2u, Bb + (size_t)row * K + ch,
                       (n0 + row) < N);
        }
        CP_COMMIT();
    };

    // prologue: exactly 3 groups committed (real or empty)
    load_tile(0, 0);
    if (KT > 1) load_tile(1, 1); else CP_COMMIT();
    if (KT > 2) load_tile(2, 2); else CP_COMMIT();

    for (int kt = 0; kt < KT; kt++) {
        // groups committed so far = 3 + kt; newest 2 are (kt+1, kt+2) → g(kt) done
        CP_WAIT2();
        __syncthreads();
        if (kt + 3 < KT) load_tile(kt + 3, (kt + 3) & 3); else CP_COMMIT();

        const uint32_t stage = smem_b + (uint32_t)((kt & 3) * STAGE_BYTES);
#pragma unroll
        for (int ks = 0; ks < 4; ks++) {
            uint32_t af[4][4], bf[8][2];
#pragma unroll
            for (int mt = 0; mt < 4; mt++)
                LDSM_X4(af[mt][0], af[mt][1], af[mt][2], af[mt][3],
                        stage + aoff[mt] + (uint32_t)(ks * 32));
#pragma unroll
            for (int p = 0; p < 4; p++)
                LDSM_X4(bf[2 * p][0], bf[2 * p][1], bf[2 * p + 1][0], bf[2 * p + 1][1],
                        stage + boff[p] + (uint32_t)(ks * 32));
#pragma unroll
            for (int mt = 0; mt < 4; mt++)
#pragma unroll
                for (int nt = 0; nt < 8; nt++)
                    mma_f16(acc[mt][nt], af[mt], bf[nt]);
        }
    }

    // epilogue
    const int ar = lane >> 2;
    const int ac = lane & 3;
#pragma unroll
    for (int mt = 0; mt < 4; mt++) {
#pragma unroll
        for (int nt = 0; nt < 8; nt++) {
            int row = m0 + wm + mt * 16 + ar;
            int col = n0 + wn + nt * 8 + ac * 2;
            if (col >= N) continue;
            float* c0 = C + (size_t)row * ldc + col;
            float* c1 = C + (size_t)(row + 8) * ldc + col;
            float v0 = acc[mt][nt][0], v1 = acc[mt][nt][1];
            float v2 = acc[mt][nt][2], v3 = acc[mt][nt][3];
            if (EPI == 1) {
                float b0 = bias[col], b1 = bias[col + 1];
                v0 = softplusf(v0 + b0); v1 = softplusf(v1 + b1);
                v2 = softplusf(v2 + b0); v3 = softplusf(v3 + b1);
            }
            if (EPI == 3) {
                atomicAdd(c0, v0); atomicAdd(c0 + 1, v1);
                atomicAdd(c1, v2); atomicAdd(c1 + 1, v3);
            } else {
                *(float2*)c0 = make_float2(v0, v1);
                *(float2*)c1 = make_float2(v2, v3);
            }
        }
    }
}

// ---------------- conversion kernels ----------------
__device__ __forceinline__ uint32_t pack_h2(float a, float b) {
    __half2 h = __floats2half2_rn(a, b);
    return *reinterpret_cast<uint32_t*>(&h);
}
__global__ void cvt_half(const float4* __restrict__ in, uint2* __restrict__ out, int n4) {
    int i = blockIdx.x * blockDim.x + threadIdx.x;
    if (i < n4) {
        float4 v = in[i];
        uint2 u;
        u.x = pack_h2(v.x, v.y);
        u.y = pack_h2(v.z, v.w);
        out[i] = u;
    }
}
// fused convert of W_in_states + W_in_gates into g_w12h
__global__ void cvt_w12(const float4* __restrict__ wis, const float4* __restrict__ wig) {
    const int NHALF = (DDI * HH) / 4;     // 2M float4 per half
    int i = blockIdx.x * blockDim.x + threadIdx.x;
    const float4* src;
    uint2* dst;
    if (i < NHALF) { src = wis + i; dst = (uint2*)g_w12h + i; }
    else if (i < 2 * NHALF) { int j = i - NHALF; src = wig + j; dst = (uint2*)(g_w12h + (size_t)DDI * HH) + j; }
    else return;
    float4 v = *src;
    uint2 u;
    u.x = pack_h2(v.x, v.y);
    u.y = pack_h2(v.z, v.w);
    *dst = u;
}
__global__ void cvt_small(const float4* __restrict__ wdtp_in, const float4* __restrict__ wdt_in,
                          const float4* __restrict__ wb_in, const float4* __restrict__ wc_in) {
    const int N_WDTP = (DDI * RR) / 4;
    const int N_WDT  = (RR * DDI) / 4;
    const int N_W16  = (NSS * DDI) / 4;
    int i = blockIdx.x * blockDim.x + threadIdx.x;
    const float4* src;
    uint2* dst;
    if (i < N_WDTP) { src = wdtp_in + i; dst = (uint2*)g_wdtph + i; }
    else if (i < N_WDTP + N_WDT) { int j = i - N_WDTP; src = wdt_in + j; dst = (uint2*)g_wdtbch + j; }
    else if (i < N_WDTP + N_WDT + N_W16) { int j = i - N_WDTP - N_WDT; src = wb_in + j; dst = (uint2*)(g_wdtbch + (size_t)RR * DDI) + j; }
    else if (i < N_WDTP + N_WDT + 2 * N_W16) { int j = i - N_WDTP - N_WDT - N_W16; src = wc_in + j; dst = (uint2*)(g_wdtbch + (size_t)(RR + NSS) * DDI) + j; }
    else return;
    float4 v = *src;
    uint2 u;
    u.x = pack_h2(v.x, v.y);
    u.y = pack_h2(v.z, v.w);
    *dst = u;
}
__global__ void zero_kernel(float* __restrict__ p, int n) {
    int i = blockIdx.x * blockDim.x + threadIdx.x;
    if (i < n) p[i] = 0.f;
}
__global__ void round_ts_kernel() {
    int i = blockIdx.x * blockDim.x + threadIdx.x;
    int l = i >> 7, r = i & 127;
    g_tsh[i] = __float2half_rn(g_tsbc[l * 160 + r]);
}

// conv (K=4, causal) + SiLU -> half
__global__ void conv_silu_kernel(const float* __restrict__ cw, const float* __restrict__ cb) {
    int idx = blockIdx.x * blockDim.x + threadIdx.x;
    int l = idx >> 12;
    int d = idx & (DDI - 1);
    float4 w = ((const float4*)cw)[d];
    float acc = cb[d];
    const float* hp = g_pg + d;
    if (l >= 3) acc = fmaf(w.x, hp[(size_t)(l - 3) * 8192], acc);
    if (l >= 2) acc = fmaf(w.y, hp[(size_t)(l - 2) * 8192], acc);
    if (l >= 1) acc = fmaf(w.z, hp[(size_t)(l - 1) * 8192], acc);
    acc = fmaf(w.w, hp[(size_t)l * 8192], acc);
    float s = acc / (1.f + __expf(-acc));
    g_hsh[idx] = __float2half_rn(s);
}

// selective scan
__global__ void scan_kernel(const float* __restrict__ A_log, const float* __restrict__ Dv) {
    int gwarp = (blockIdx.x * blockDim.x + threadIdx.x) >> 5;
    int lane = threadIdx.x & 31;
    int c = lane >> 4;
    int n = lane & 15;
    int d = gwarp * 2 + c;

    const float Acoef = -__expf(A_log[d * NSS + n]);
    const float Dd = Dv[d];
    float s = 0.f;
#pragma unroll 2
    for (int l = 0; l < LL; l++) {
        float dtv = g_dt[(size_t)l * DDI + d];
        float hsv = __half2float(g_hsh[(size_t)l * DDI + d]);
        float Bv = g_tsbc[l * 160 + 128 + n];
        float Cv = g_tsbc[l * 160 + 144 + n];
        float a = __expf(Acoef * dtv);
        s = fmaf(a, s, dtv * Bv * hsv);
        float v = s * Cv;
        v += __shfl_xor_sync(0xFFFFFFFFu, v, 1);
        v += __shfl_xor_sync(0xFFFFFFFFu, v, 2);
        v += __shfl_xor_sync(0xFFFFFFFFu, v, 4);
        v += __shfl_xor_sync(0xFFFFFFFFu, v, 8);
        if (n == 0) {
            float gv = g_pg[(size_t)l * 8192 + 4096 + d];
            float y = (v + hsv * Dd) * (gv / (1.f + __expf(-gv)));
            g_yh[(size_t)l * DDI + d] = __float2half_rn(y);
        }
    }
}

// ---------------- host ----------------
extern "C" void kernel_launch(void* const* d_in, const int* in_sizes, int n_in,
                              void* d_out, int out_size)
{
    const float* x           = (const float*)d_in[0];
    const float* W_in_states = (const float*)d_in[1];
    const float* W_in_gates  = (const float*)d_in[2];
    const float* conv_w      = (const float*)d_in[3];
    const float* conv_b      = (const float*)d_in[4];
    const float* W_dt        = (const float*)d_in[5];
    const float* W_b         = (const float*)d_in[6];
    const float* W_c         = (const float*)d_in[7];
    const float* W_dtproj    = (const float*)d_in[8];
    const float* b_dtproj    = (const float*)d_in[9];
    const float* A_log       = (const float*)d_in[10];
    const float* Dv          = (const float*)d_in[11];
    const float* W_out       = (const float*)d_in[12];
    float* out = (float*)d_out;

    float *pg, *dt, *tsbc;
    __half *hsh, *tsh, *yh, *xh, *w12h, *wouth, *wdtbch, *wdtph;
    cudaGetSymbolAddress((void**)&pg,     g_pg);
    cudaGetSymbolAddress((void**)&dt,     g_dt);
    cudaGetSymbolAddress((void**)&tsbc,   g_tsbc);
    cudaGetSymbolAddress((void**)&hsh,    g_hsh);
    cudaGetSymbolAddress((void**)&tsh,    g_tsh);
    cudaGetSymbolAddress((void**)&yh,     g_yh);
    cudaGetSymbolAddress((void**)&xh,     g_xh);
    cudaGetSymbolAddress((void**)&w12h,   g_w12h);
    cudaGetSymbolAddress((void**)&wouth,  g_wouth);
    cudaGetSymbolAddress((void**)&wdtbch, g_wdtbch);
    cudaGetSymbolAddress((void**)&wdtph,  g_wdtph);

    const int SMEM = NSTAGE * STAGE_BYTES;   // 221184 bytes
    cudaFuncSetAttribute(gemm_mma<0>, cudaFuncAttributeMaxDynamicSharedMemorySize, SMEM);
    cudaFuncSetAttribute(gemm_mma<1>, cudaFuncAttributeMaxDynamicSharedMemorySize, SMEM);
    cudaFuncSetAttribute(gemm_mma<3>, cudaFuncAttributeMaxDynamicSharedMemorySize, SMEM);

    // launch 0: convert x
    {
        int n4 = (LL * HH) / 4;
        cvt_half<<<(n4 + 255) / 256, 256>>>((const float4*)x, (uint2*)xh, n4);
    }
    // launch 1: fused convert of both input-proj weights
    {
        int total4 = (2 * DDI * HH) / 4;
        cvt_w12<<<(total4 + 255) / 256, 256>>>((const float4*)W_in_states, (const float4*)W_in_gates);
    }
    // launches 2+3: G12 split into two N=4096 halves (profiling target)
    gemm_mma<0><<<dim3(DDI / BN, LL / BM), 256, SMEM>>>(xh, w12h, pg, nullptr, LL, DDI, HH, 2 * DDI);
    gemm_mma<0><<<dim3(DDI / BN, LL / BM), 256, SMEM>>>(xh, w12h + (size_t)DDI * HH, pg + DDI, nullptr, LL, DDI, HH, 2 * DDI);
    // remaining converts
    {
        int n4 = (HH * DDI) / 4;
        cvt_half<<<(n4 + 255) / 256, 256>>>((const float4*)W_out, (uint2*)wouth, n4);
    }
    {
        int total4 = (DDI * RR + RR * DDI + 2 * NSS * DDI) / 4;
        cvt_small<<<(total4 + 255) / 256, 256>>>((const float4*)W_dtproj, (const float4*)W_dt,
                                                 (const float4*)W_b, (const float4*)W_c);
    }
    // conv + silu -> hsh
    conv_silu_kernel<<<(LL * DDI) / 256, 256>>>(conv_w, conv_b);
    // zero split-K accumulator
    zero_kernel<<<(LL * 160 + 255) / 256, 256>>>(tsbc, LL * 160);
    // G35 (split-K=8, atomic): tsbc[L, 160] = hs . [W_dt; W_b; W_c]^T
    gemm_mma<3><<<dim3(1, LL / BM, 8), 256, SMEM>>>(hsh, wdtbch, tsbc, nullptr, LL, 160, DDI, 160);
    // round ts slice -> half
    round_ts_kernel<<<(LL * RR) / 256, 256>>>();
    // G4: dt[L, DI] = softplus(ts . W_dtproj^T + b)
    gemm_mma<1><<<dim3(DDI / BN, LL / BM), 256, SMEM>>>(tsh, wdtph, dt, b_dtproj, LL, DDI, RR, DDI);
    // scan + gating -> yh
    scan_kernel<<<(DDI / 2 * 32) / 256, 256>>>(A_log, Dv);
    // zero output, then G6 (split-K=2, atomic): out = y . W_out^T
    zero_kernel<<<(LL * HH + 255) / 256, 256>>>(out, LL * HH);
    gemm_mma<3><<<dim3(HH / BN, LL / BM, 2), 256, SMEM>>>(yh, wouth, out, nullptr, LL, HH, DDI, HH);
}

// round 12
// speedup vs baseline: 1.0131x; 1.0131x over previous
#include <cuda_runtime.h>
#include <cuda_fp16.h>
#include <cstdint>

#define LL 1024
#define HH 2048
#define DDI 4096
#define NSS 16
#define RR 128

// ---------------- scratch ----------------
__device__ float  g_pg   [LL * 2 * DDI];   // [l,0:4096]=hs_pre, [l,4096:8192]=gate (fp32)
__device__ __half g_hsh  [LL * DDI];
__device__ __half g_tsh  [LL * RR];
__device__ float  g_dt   [LL * DDI];
__device__ float  g_tsbc [LL * 160];       // split-K accum: ts(128)|B(16)|C(16)
__device__ __half g_yh   [LL * DDI];
// half operand copies
__device__ __half g_xh   [LL * HH];
__device__ __half g_w12h [2 * DDI * HH];
__device__ __half g_wouth[HH * DDI];
__device__ __half g_wdtbch[160 * DDI];
__device__ __half g_wdtph [DDI * RR];

// ---------------- helpers ----------------
__device__ __forceinline__ uint32_t smem_u32(const void* p) {
    uint32_t a;
    asm("{ .reg .u64 t; cvta.to.shared.u64 t, %1; cvt.u32.u64 %0, t; }" : "=r"(a) : "l"(p));
    return a;
}
__device__ __forceinline__ void cp_async16(uint32_t dst, const void* src, bool pred) {
    int bytes = pred ? 16 : 0;
    asm volatile("cp.async.cg.shared.global [%0], [%1], 16, %2;" :: "r"(dst), "l"(src), "r"(bytes));
}
#define CP_COMMIT() asm volatile("cp.async.commit_group;" ::: "memory")
#define CP_WAIT1()  asm volatile("cp.async.wait_group 1;" ::: "memory")
#define CP_WAIT0()  asm volatile("cp.async.wait_group 0;" ::: "memory")

__device__ __forceinline__ float softplusf(float x) {
    return (x > 20.f) ? x : log1pf(expf(x));
}
__device__ __forceinline__ void mma_f16(float* c, const uint32_t* a, const uint32_t* b) {
    asm volatile(
        "mma.sync.aligned.m16n8k16.row.col.f32.f16.f16.f32 "
        "{%0,%1,%2,%3}, {%4,%5,%6,%7}, {%8,%9}, {%0,%1,%2,%3};"
        : "+f"(c[0]), "+f"(c[1]), "+f"(c[2]), "+f"(c[3])
        : "r"(a[0]), "r"(a[1]), "r"(a[2]), "r"(a[3]), "r"(b[0]), "r"(b[1]));
}
#define LDSM_X4(r0, r1, r2, r3, addr) \
    asm volatile("ldmatrix.sync.aligned.m8n8.x4.shared.b16 {%0,%1,%2,%3}, [%4];" \
                 : "=r"(r0), "=r"(r1), "=r"(r2), "=r"(r3) : "r"(addr))

// ---------------- fp16 mma.sync GEMM: C[M,N] = A[M,K] . B[N,K]^T ----------------
// CTA tile 256x128, 512 threads = 16 warps (4x4), warp tile 64x32, BK=64 halfs,
// 3-stage cp.async (2 tiles in flight). acc=64 regs/thread -> ~120 regs, 16 warps/SM.
// EPI: 0 plain, 1 softplus(acc+bias[n]), 3 atomicAdd (split-K over gridDim.z)
#define BM 256
#define BN 128
#define TROWS (BM + BN)                 // 384
#define SAPADH 72                        // halfs per row (144B)
#define STAGE_BYTES (TROWS * SAPADH * 2) // 55296
#define NSTAGE 3
#define NTHREADS 512

template<int EPI>
__global__ __launch_bounds__(NTHREADS, 1) void gemm_mma(
    const __half* __restrict__ A, const __half* __restrict__ B, float* __restrict__ C,
    const float* __restrict__ bias, int M, int N, int K, int ldc)
{
    extern __shared__ __half smem[];
    const int tid = threadIdx.x;
    const int wid = tid >> 5;
    const int lane = tid & 31;
    const int m0 = blockIdx.y * BM;
    const int n0 = blockIdx.x * BN;
    const int Ksplit = K / gridDim.z;
    const int kbase = blockIdx.z * Ksplit;
    const int KT = Ksplit >> 6;          // BK = 64

    const int wm = (wid & 3) * 64;       // 4 warps in M
    const int wn = (wid >> 2) * 32;      // 4 warps in N

    float acc[4][4][4];
#pragma unroll
    for (int i = 0; i < 4; i++)
#pragma unroll
        for (int j = 0; j < 4; j++)
#pragma unroll
            for (int r = 0; r < 4; r++) acc[i][j][r] = 0.f;

    const uint32_t smem_b = smem_u32(smem);

    uint32_t aoff[4], boff[2];
    {
        const int arow = lane & 15;
        const int acolh = (lane >> 4) * 8;
#pragma unroll
        for (int mt = 0; mt < 4; mt++)
            aoff[mt] = (uint32_t)(((wm + mt * 16 + arow) * SAPADH + acolh) * 2);
        const int bg = lane >> 3;
        const int br = lane & 7;
        const int nadd = (bg >> 1) * 8;
        const int khalf = (bg & 1) * 8;
#pragma unroll
        for (int p = 0; p < 2; p++)
            boff[p] = (uint32_t)(((BM + wn + 16 * p + nadd + br) * SAPADH + khalf) * 2);
    }

    auto load_tile = [&](int kt, int s) {
        const uint32_t a_s = smem_b + (uint32_t)(s * STAGE_BYTES);
        const uint32_t b_s = a_s + (uint32_t)(BM * SAPADH * 2);
        const int k0 = kbase + (kt << 6);
        const __half* Ab = A + (size_t)m0 * K + k0;
        const __half* Bb = B + (size_t)n0 * K + k0;
#pragma unroll
        for (int i = 0; i < 4; i++) {        // A: 256 rows x 8 chunks = 2048 / 512
            int idx = tid + i * NTHREADS;
            int row = idx >> 3;
            int ch = (idx & 7) << 3;
            cp_async16(a_s + (uint32_t)(row * SAPADH + ch) * 2u, Ab + (size_t)row * K + ch, true);
        }
#pragma unroll
        for (int i = 0; i < 2; i++) {        // B: 128 rows x 8 chunks = 1024 / 512
            int idx = tid + i * NTHREADS;
            int row = idx >> 3;
            int ch = (idx & 7) << 3;
            cp_async16(b_s + (uint32_t)(row * SAPADH + ch) * 2u, Bb + (size_t)row * K + ch,
                       (n0 + row) < N);
        }
        CP_COMMIT();
    };

    load_tile(0, 0);
    if (KT > 1) load_tile(1, 1); else CP_COMMIT();

    for (int kt = 0; kt < KT; kt++) {
        if (kt == KT - 1) { CP_WAIT0(); } else { CP_WAIT1(); }
        __syncthreads();
        if (kt + 2 < KT) load_tile(kt + 2, (kt + 2) % NSTAGE);

        const uint32_t stage = smem_b + (uint32_t)((kt % NSTAGE) * STAGE_BYTES);
#pragma unroll
        for (int ks = 0; ks < 4; ks++) {
            uint32_t af[4][4], bf[4][2];
#pragma unroll
            for (int mt = 0; mt < 4; mt++)
                LDSM_X4(af[mt][0], af[mt][1], af[mt][2], af[mt][3],
                        stage + aoff[mt] + (uint32_t)(ks * 32));
#pragma unroll
            for (int p = 0; p < 2; p++)
                LDSM_X4(bf[2 * p][0], bf[2 * p][1], bf[2 * p + 1][0], bf[2 * p + 1][1],
                        stage + boff[p] + (uint32_t)(ks * 32));
#pragma unroll
            for (int mt = 0; mt < 4; mt++)
#pragma unroll
                for (int nt = 0; nt < 4; nt++)
                    mma_f16(acc[mt][nt], af[mt], bf[nt]);
        }
    }

    // epilogue
    const int ar = lane >> 2;
    const int ac = lane & 3;
#pragma unroll
    for (int mt = 0; mt < 4; mt++) {
#pragma unroll
        for (int nt = 0; nt < 4; nt++) {
            int row = m0 + wm + mt * 16 + ar;
            int col = n0 + wn + nt * 8 + ac * 2;
            if (col >= N) continue;
            float* c0 = C + (size_t)row * ldc + col;
            float* c1 = C + (size_t)(row + 8) * ldc + col;
            float v0 = acc[mt][nt][0], v1 = acc[mt][nt][1];
            float v2 = acc[mt][nt][2], v3 = acc[mt][nt][3];
            if (EPI == 1) {
                float b0 = bias[col], b1 = bias[col + 1];
                v0 = softplusf(v0 + b0); v1 = softplusf(v1 + b1);
                v2 = softplusf(v2 + b0); v3 = softplusf(v3 + b1);
            }
            if (EPI == 3) {
                atomicAdd(c0, v0); atomicAdd(c0 + 1, v1);
                atomicAdd(c1, v2); atomicAdd(c1 + 1, v3);
            } else {
                *(float2*)c0 = make_float2(v0, v1);
                *(float2*)c1 = make_float2(v2, v3);
            }
        }
    }
}

// ---------------- conversion kernels ----------------
__device__ __forceinline__ uint32_t pack_h2(float a, float b) {
    __half2 h = __floats2half2_rn(a, b);
    return *reinterpret_cast<uint32_t*>(&h);
}
__global__ void cvt_half(const float4* __restrict__ in, uint2* __restrict__ out, int n4) {
    int i = blockIdx.x * blockDim.x + threadIdx.x;
    if (i < n4) {
        float4 v = in[i];
        uint2 u;
        u.x = pack_h2(v.x, v.y);
        u.y = pack_h2(v.z, v.w);
        out[i] = u;
    }
}
__global__ void cvt_w12(const float4* __restrict__ wis, const float4* __restrict__ wig) {
    const int NHALF = (DDI * HH) / 4;
    int i = blockIdx.x * blockDim.x + threadIdx.x;
    const float4* src;
    uint2* dst;
    if (i < NHALF) { src = wis + i; dst = (uint2*)g_w12h + i; }
    else if (i < 2 * NHALF) { int j = i - NHALF; src = wig + j; dst = (uint2*)(g_w12h + (size_t)DDI * HH) + j; }
    else return;
    float4 v = *src;
    uint2 u;
    u.x = pack_h2(v.x, v.y);
    u.y = pack_h2(v.z, v.w);
    *dst = u;
}
__global__ void cvt_small(const float4* __restrict__ wdtp_in, const float4* __restrict__ wdt_in,
                          const float4* __restrict__ wb_in, const float4* __restrict__ wc_in) {
    const int N_WDTP = (DDI * RR) / 4;
    const int N_WDT  = (RR * DDI) / 4;
    const int N_W16  = (NSS * DDI) / 4;
    int i = blockIdx.x * blockDim.x + threadIdx.x;
    const float4* src;
    uint2* dst;
    if (i < N_WDTP) { src = wdtp_in + i; dst = (uint2*)g_wdtph + i; }
    else if (i < N_WDTP + N_WDT) { int j = i - N_WDTP; src = wdt_in + j; dst = (uint2*)g_wdtbch + j; }
    else if (i < N_WDTP + N_WDT + N_W16) { int j = i - N_WDTP - N_WDT; src = wb_in + j; dst = (uint2*)(g_wdtbch + (size_t)RR * DDI) + j; }
    else if (i < N_WDTP + N_WDT + 2 * N_W16) { int j = i - N_WDTP - N_WDT - N_W16; src = wc_in + j; dst = (uint2*)(g_wdtbch + (size_t)(RR + NSS) * DDI) + j; }
    else return;
    float4 v = *src;
    uint2 u;
    u.x = pack_h2(v.x, v.y);
    u.y = pack_h2(v.z, v.w);
    *dst = u;
}
__global__ void zero_kernel(float* __restrict__ p, int n) {
    int i = blockIdx.x * blockDim.x + threadIdx.x;
    if (i < n) p[i] = 0.f;
}
__global__ void round_ts_kernel() {
    int i = blockIdx.x * blockDim.x + threadIdx.x;
    int l = i >> 7, r = i & 127;
    g_tsh[i] = __float2half_rn(g_tsbc[l * 160 + r]);
}

// conv (K=4, causal) + SiLU -> half
__global__ void conv_silu_kernel(const float* __restrict__ cw, const float* __restrict__ cb) {
    int idx = blockIdx.x * blockDim.x + threadIdx.x;
    int l = idx >> 12;
    int d = idx & (DDI - 1);
    float4 w = ((const float4*)cw)[d];
    float acc = cb[d];
    const float* hp = g_pg + d;
    if (l >= 3) acc = fmaf(w.x, hp[(size_t)(l - 3) * 8192], acc);
    if (l >= 2) acc = fmaf(w.y, hp[(size_t)(l - 2) * 8192], acc);
    if (l >= 1) acc = fmaf(w.z, hp[(size_t)(l - 1) * 8192], acc);
    acc = fmaf(w.w, hp[(size_t)l * 8192], acc);
    float s = acc / (1.f + __expf(-acc));
    g_hsh[idx] = __float2half_rn(s);
}

// selective scan
__global__ void scan_kernel(const float* __restrict__ A_log, const float* __restrict__ Dv) {
    int gwarp = (blockIdx.x * blockDim.x + threadIdx.x) >> 5;
    int lane = threadIdx.x & 31;
    int c = lane >> 4;
    int n = lane & 15;
    int d = gwarp * 2 + c;

    const float Acoef = -__expf(A_log[d * NSS + n]);
    const float Dd = Dv[d];
    float s = 0.f;
#pragma unroll 2
    for (int l = 0; l < LL; l++) {
        float dtv = g_dt[(size_t)l * DDI + d];
        float hsv = __half2float(g_hsh[(size_t)l * DDI + d]);
        float Bv = g_tsbc[l * 160 + 128 + n];
        float Cv = g_tsbc[l * 160 + 144 + n];
        float a = __expf(Acoef * dtv);
        s = fmaf(a, s, dtv * Bv * hsv);
        float v = s * Cv;
        v += __shfl_xor_sync(0xFFFFFFFFu, v, 1);
        v += __shfl_xor_sync(0xFFFFFFFFu, v, 2);
        v += __shfl_xor_sync(0xFFFFFFFFu, v, 4);
        v += __shfl_xor_sync(0xFFFFFFFFu, v, 8);
        if (n == 0) {
            float gv = g_pg[(size_t)l * 8192 + 4096 + d];
            float y = (v + hsv * Dd) * (gv / (1.f + __expf(-gv)));
            g_yh[(size_t)l * DDI + d] = __float2half_rn(y);
        }
    }
}

// ---------------- host ----------------
extern "C" void kernel_launch(void* const* d_in, const int* in_sizes, int n_in,
                              void* d_out, int out_size)
{
    const float* x           = (const float*)d_in[0];
    const float* W_in_states = (const float*)d_in[1];
    const float* W_in_gates  = (const float*)d_in[2];
    const float* conv_w      = (const float*)d_in[3];
    const float* conv_b      = (const float*)d_in[4];
    const float* W_dt        = (const float*)d_in[5];
    const float* W_b         = (const float*)d_in[6];
    const float* W_c         = (const float*)d_in[7];
    const float* W_dtproj    = (const float*)d_in[8];
    const float* b_dtproj    = (const float*)d_in[9];
    const float* A_log       = (const float*)d_in[10];
    const float* Dv          = (const float*)d_in[11];
    const float* W_out       = (const float*)d_in[12];
    float* out = (float*)d_out;

    float *pg, *dt, *tsbc;
    __half *hsh, *tsh, *yh, *xh, *w12h, *wouth, *wdtbch, *wdtph;
    cudaGetSymbolAddress((void**)&pg,     g_pg);
    cudaGetSymbolAddress((void**)&dt,     g_dt);
    cudaGetSymbolAddress((void**)&tsbc,   g_tsbc);
    cudaGetSymbolAddress((void**)&hsh,    g_hsh);
    cudaGetSymbolAddress((void**)&tsh,    g_tsh);
    cudaGetSymbolAddress((void**)&yh,     g_yh);
    cudaGetSymbolAddress((void**)&xh,     g_xh);
    cudaGetSymbolAddress((void**)&w12h,   g_w12h);
    cudaGetSymbolAddress((void**)&wouth,  g_wouth);
    cudaGetSymbolAddress((void**)&wdtbch, g_wdtbch);
    cudaGetSymbolAddress((void**)&wdtph,  g_wdtph);

    const int SMEM = NSTAGE * STAGE_BYTES;   // 165888 bytes
    cudaFuncSetAttribute(gemm_mma<0>, cudaFuncAttributeMaxDynamicSharedMemorySize, SMEM);
    cudaFuncSetAttribute(gemm_mma<1>, cudaFuncAttributeMaxDynamicSharedMemorySize, SMEM);
    cudaFuncSetAttribute(gemm_mma<3>, cudaFuncAttributeMaxDynamicSharedMemorySize, SMEM);

    // launch 0: convert x
    {
        int n4 = (LL * HH) / 4;
        cvt_half<<<(n4 + 255) / 256, 256>>>((const float4*)x, (uint2*)xh, n4);
    }
    // launch 1: fused convert of both input-proj weights
    {
        int total4 = (2 * DDI * HH) / 4;
        cvt_w12<<<(total4 + 255) / 256, 256>>>((const float4*)W_in_states, (const float4*)W_in_gates);
    }
    // launch 2: G12 (single launch): pg[L, 8192] = x . [W_in_states; W_in_gates]^T
    gemm_mma<0><<<dim3(2 * DDI / BN, LL / BM), NTHREADS, SMEM>>>(xh, w12h, pg, nullptr, LL, 2 * DDI, HH, 2 * DDI);
    // remaining converts
    {
        int n4 = (HH * DDI) / 4;
        cvt_half<<<(n4 + 255) / 256, 256>>>((const float4*)W_out, (uint2*)wouth, n4);
    }
    {
        int total4 = (DDI * RR + RR * DDI + 2 * NSS * DDI) / 4;
        cvt_small<<<(total4 + 255) / 256, 256>>>((const float4*)W_dtproj, (const float4*)W_dt,
                                                 (const float4*)W_b, (const float4*)W_c);
    }
    // conv + silu -> hsh
    conv_silu_kernel<<<(LL * DDI) / 256, 256>>>(conv_w, conv_b);
    // zero split-K accumulator
    zero_kernel<<<(LL * 160 + 255) / 256, 256>>>(tsbc, LL * 160);
    // G35 (split-K=8, atomic): tsbc[L, 160] = hs . [W_dt; W_b; W_c]^T
    gemm_mma<3><<<dim3(2, LL / BM, 8), NTHREADS, SMEM>>>(hsh, wdtbch, tsbc, nullptr, LL, 160, DDI, 160);
    // round ts slice -> half
    round_ts_kernel<<<(LL * RR) / 256, 256>>>();
    // G4: dt[L, DI] = softplus(ts . W_dtproj^T + b)
    gemm_mma<1><<<dim3(DDI / BN, LL / BM), NTHREADS, SMEM>>>(tsh, wdtph, dt, b_dtproj, LL, DDI, RR, DDI);
    // scan + gating -> yh
    scan_kernel<<<(DDI / 2 * 32) / 256, 256>>>(A_log, Dv);
    // zero output, then G6 (split-K=2, atomic): out = y . W_out^T
    zero_kernel<<<(LL * HH + 255) / 256, 256>>>(out, LL * HH);
    gemm_mma<3><<<dim3(HH / BN, LL / BM, 2), NTHREADS, SMEM>>>(yh, wouth, out, nullptr, LL, HH, DDI, HH);
}

// round 13
// speedup vs baseline: 2.0957x; 2.0687x over previous
#include <cuda_runtime.h>
#include <cuda_fp16.h>
#include <cstdint>

#define LL 1024
#define HH 2048
#define DDI 4096
#define NSS 16
#define RR 128

// ---------------- scratch ----------------
__device__ float  g_pg   [LL * 2 * DDI];   // [l,0:4096]=hs_pre, [l,4096:8192]=gate (fp32)
__device__ __half g_hsh  [LL * DDI];
__device__ __half g_tsh  [LL * RR];
__device__ float  g_dt   [LL * DDI];
__device__ float  g_tsbc [LL * 160];       // split-K accum: ts(128)|B(16)|C(16)
__device__ __half g_yh   [LL * DDI];
// half operand copies
__device__ __half g_xh   [LL * HH];
__device__ __half g_w12h [2 * DDI * HH];
__device__ __half g_wouth[HH * DDI];
__device__ __half g_wdtbch[160 * DDI];
__device__ __half g_wdtph [DDI * RR];

// ---------------- helpers ----------------
__device__ __forceinline__ uint32_t smem_u32(const void* p) {
    uint32_t a;
    asm("{ .reg .u64 t; cvta.to.shared.u64 t, %1; cvt.u32.u64 %0, t; }" : "=r"(a) : "l"(p));
    return a;
}
__device__ __forceinline__ void cp_async16(uint32_t dst, const void* src, bool pred) {
    int bytes = pred ? 16 : 0;
    asm volatile("cp.async.cg.shared.global [%0], [%1], 16, %2;" :: "r"(dst), "l"(src), "r"(bytes));
}
#define CP_COMMIT() asm volatile("cp.async.commit_group;" ::: "memory")
#define CP_WAIT1()  asm volatile("cp.async.wait_group 1;" ::: "memory")
#define CP_WAIT0()  asm volatile("cp.async.wait_group 0;" ::: "memory")

__device__ __forceinline__ float softplusf(float x) {
    return (x > 20.f) ? x : log1pf(expf(x));
}
__device__ __forceinline__ void mma_f16(float* c, const uint32_t* a, const uint32_t* b) {
    asm volatile(
        "mma.sync.aligned.m16n8k16.row.col.f32.f16.f16.f32 "
        "{%0,%1,%2,%3}, {%4,%5,%6,%7}, {%8,%9}, {%0,%1,%2,%3};"
        : "+f"(c[0]), "+f"(c[1]), "+f"(c[2]), "+f"(c[3])
        : "r"(a[0]), "r"(a[1]), "r"(a[2]), "r"(a[3]), "r"(b[0]), "r"(b[1]));
}
#define LDSM_X4(r0, r1, r2, r3, addr) \
    asm volatile("ldmatrix.sync.aligned.m8n8.x4.shared.b16 {%0,%1,%2,%3}, [%4];" \
                 : "=r"(r0), "=r"(r1), "=r"(r2), "=r"(r3) : "r"(addr))

// ---------------- fp16 mma.sync GEMM (R8 measured-best config) ----------------
// CTA tile 128x256, warp tile 64x64 (8 warps 2x4), BK=64 halfs, 3-stage cp.async.
// EPI: 0 plain, 1 softplus(acc+bias[n]), 3 atomicAdd (split-K over gridDim.z)
#define BM 128
#define BN 256
#define TROWS (BM + BN)                 // 384
#define SAPADH 72                        // halfs per row (144B)
#define STAGE_BYTES (TROWS * SAPADH * 2) // 55296
#define NSTAGE 3

template<int EPI>
__global__ __launch_bounds__(256, 1) void gemm_mma(
    const __half* __restrict__ A, const __half* __restrict__ B, float* __restrict__ C,
    const float* __restrict__ bias, int M, int N, int K, int ldc)
{
    extern __shared__ __half smem[];
    const int tid = threadIdx.x;
    const int wid = tid >> 5;
    const int lane = tid & 31;
    const int m0 = blockIdx.y * BM;
    const int n0 = blockIdx.x * BN;
    const int Ksplit = K / gridDim.z;
    const int kbase = blockIdx.z * Ksplit;
    const int KT = Ksplit >> 6;          // BK = 64

    const int wm = (wid >> 2) * 64;
    const int wn = (wid & 3) * 64;

    float acc[4][8][4];
#pragma unroll
    for (int i = 0; i < 4; i++)
#pragma unroll
        for (int j = 0; j < 8; j++)
#pragma unroll
            for (int r = 0; r < 4; r++) acc[i][j][r] = 0.f;

    const uint32_t smem_b = smem_u32(smem);

    uint32_t aoff[4], boff[4];
    {
        const int arow = lane & 15;
        const int acolh = (lane >> 4) * 8;
#pragma unroll
        for (int mt = 0; mt < 4; mt++)
            aoff[mt] = (uint32_t)(((wm + mt * 16 + arow) * SAPADH + acolh) * 2);
        const int bg = lane >> 3;
        const int br = lane & 7;
        const int nadd = (bg >> 1) * 8;
        const int khalf = (bg & 1) * 8;
#pragma unroll
        for (int p = 0; p < 4; p++)
            boff[p] = (uint32_t)(((BM + wn + 16 * p + nadd + br) * SAPADH + khalf) * 2);
    }

    auto load_tile = [&](int kt, int s) {
        const uint32_t a_s = smem_b + (uint32_t)(s * STAGE_BYTES);
        const uint32_t b_s = a_s + (uint32_t)(BM * SAPADH * 2);
        const int k0 = kbase + (kt << 6);
        const __half* Ab = A + (size_t)m0 * K + k0;
        const __half* Bb = B + (size_t)n0 * K + k0;
#pragma unroll
        for (int i = 0; i < 4; i++) {
            int idx = tid + i * 256;
            int row = idx >> 3;
            int ch = (idx & 7) << 3;
            cp_async16(a_s + (uint32_t)(row * SAPADH + ch) * 2u, Ab + (size_t)row * K + ch, true);
        }
#pragma unroll
        for (int i = 0; i < 8; i++) {
            int idx = tid + i * 256;
            int row = idx >> 3;
            int ch = (idx & 7) << 3;
            cp_async16(b_s + (uint32_t)(row * SAPADH + ch) * 2u, Bb + (size_t)row * K + ch,
                       (n0 + row) < N);
        }
        CP_COMMIT();
    };

    load_tile(0, 0);
    if (KT > 1) load_tile(1, 1); else CP_COMMIT();

    for (int kt = 0; kt < KT; kt++) {
        if (kt == KT - 1) { CP_WAIT0(); } else { CP_WAIT1(); }
        __syncthreads();
        if (kt + 2 < KT) load_tile(kt + 2, (kt + 2) % NSTAGE);

        const uint32_t stage = smem_b + (uint32_t)((kt % NSTAGE) * STAGE_BYTES);
#pragma unroll
        for (int ks = 0; ks < 4; ks++) {
            uint32_t af[4][4], bf[8][2];
#pragma unroll
            for (int mt = 0; mt < 4; mt++)
                LDSM_X4(af[mt][0], af[mt][1], af[mt][2], af[mt][3],
                        stage + aoff[mt] + (uint32_t)(ks * 32));
#pragma unroll
            for (int p = 0; p < 4; p++)
                LDSM_X4(bf[2 * p][0], bf[2 * p][1], bf[2 * p + 1][0], bf[2 * p + 1][1],
                        stage + boff[p] + (uint32_t)(ks * 32));
#pragma unroll
            for (int mt = 0; mt < 4; mt++)
#pragma unroll
                for (int nt = 0; nt < 8; nt++)
                    mma_f16(acc[mt][nt], af[mt], bf[nt]);
        }
    }

    // epilogue
    const int ar = lane >> 2;
    const int ac = lane & 3;
#pragma unroll
    for (int mt = 0; mt < 4; mt++) {
#pragma unroll
        for (int nt = 0; nt < 8; nt++) {
            int row = m0 + wm + mt * 16 + ar;
            int col = n0 + wn + nt * 8 + ac * 2;
            if (col >= N) continue;
            float* c0 = C + (size_t)row * ldc + col;
            float* c1 = C + (size_t)(row + 8) * ldc + col;
            float v0 = acc[mt][nt][0], v1 = acc[mt][nt][1];
            float v2 = acc[mt][nt][2], v3 = acc[mt][nt][3];
            if (EPI == 1) {
                float b0 = bias[col], b1 = bias[col + 1];
                v0 = softplusf(v0 + b0); v1 = softplusf(v1 + b1);
                v2 = softplusf(v2 + b0); v3 = softplusf(v3 + b1);
            }
            if (EPI == 3) {
                atomicAdd(c0, v0); atomicAdd(c0 + 1, v1);
                atomicAdd(c1, v2); atomicAdd(c1 + 1, v3);
            } else {
                *(float2*)c0 = make_float2(v0, v1);
                *(float2*)c1 = make_float2(v2, v3);
            }
        }
    }
}

// ---------------- conversion kernels ----------------
__device__ __forceinline__ uint32_t pack_h2(float a, float b) {
    __half2 h = __floats2half2_rn(a, b);
    return *reinterpret_cast<uint32_t*>(&h);
}
__global__ void cvt_half(const float4* __restrict__ in, uint2* __restrict__ out, int n4) {
    int i = blockIdx.x * blockDim.x + threadIdx.x;
    if (i < n4) {
        float4 v = in[i];
        uint2 u;
        u.x = pack_h2(v.x, v.y);
        u.y = pack_h2(v.z, v.w);
        out[i] = u;
    }
}
__global__ void cvt_small(const float4* __restrict__ wdtp_in, const float4* __restrict__ wdt_in,
                          const float4* __restrict__ wb_in, const float4* __restrict__ wc_in) {
    const int N_WDTP = (DDI * RR) / 4;
    const int N_WDT  = (RR * DDI) / 4;
    const int N_W16  = (NSS * DDI) / 4;
    int i = blockIdx.x * blockDim.x + threadIdx.x;
    const float4* src;
    uint2* dst;
    if (i < N_WDTP) { src = wdtp_in + i; dst = (uint2*)g_wdtph + i; }
    else if (i < N_WDTP + N_WDT) { int j = i - N_WDTP; src = wdt_in + j; dst = (uint2*)g_wdtbch + j; }
    else if (i < N_WDTP + N_WDT + N_W16) { int j = i - N_WDTP - N_WDT; src = wb_in + j; dst = (uint2*)(g_wdtbch + (size_t)RR * DDI) + j; }
    else if (i < N_WDTP + N_WDT + 2 * N_W16) { int j = i - N_WDTP - N_WDT - N_W16; src = wc_in + j; dst = (uint2*)(g_wdtbch + (size_t)(RR + NSS) * DDI) + j; }
    else return;
    float4 v = *src;
    uint2 u;
    u.x = pack_h2(v.x, v.y);
    u.y = pack_h2(v.z, v.w);
    *dst = u;
}
__global__ void zero_kernel(float* __restrict__ p, int n) {
    int i = blockIdx.x * blockDim.x + threadIdx.x;
    if (i < n) p[i] = 0.f;
}
__global__ void round_ts_kernel() {
    int i = blockIdx.x * blockDim.x + threadIdx.x;
    int l = i >> 7, r = i & 127;
    g_tsh[i] = __float2half_rn(g_tsbc[l * 160 + r]);
}

// conv (K=4, causal) + SiLU -> half
__global__ void conv_silu_kernel(const float* __restrict__ cw, const float* __restrict__ cb) {
    int idx = blockIdx.x * blockDim.x + threadIdx.x;
    int l = idx >> 12;
    int d = idx & (DDI - 1);
    float4 w = ((const float4*)cw)[d];
    float acc = cb[d];
    const float* hp = g_pg + d;
    if (l >= 3) acc = fmaf(w.x, hp[(size_t)(l - 3) * 8192], acc);
    if (l >= 2) acc = fmaf(w.y, hp[(size_t)(l - 2) * 8192], acc);
    if (l >= 1) acc = fmaf(w.z, hp[(size_t)(l - 1) * 8192], acc);
    acc = fmaf(w.w, hp[(size_t)l * 8192], acc);
    float s = acc / (1.f + __expf(-acc));
    g_hsh[idx] = __float2half_rn(s);
}

// ---------------- selective scan: register-blocked (chunk=16) ----------------
// warp = 2 channels (lanes 0-15 / 16-31), lane&15 = state n.
// All loads for a 16-step chunk are issued before the serial compute, so the
// DRAM/L2 latency is amortized 16x instead of paid per step.
#define SCH 16
__global__ void scan_kernel(const float* __restrict__ A_log, const float* __restrict__ Dv) {
    int gwarp = (blockIdx.x * blockDim.x + threadIdx.x) >> 5;
    int lane = threadIdx.x & 31;
    int c = lane >> 4;
    int n = lane & 15;
    int d = gwarp * 2 + c;

    const float Acoef = -__expf(A_log[d * NSS + n]);
    const float Dd = Dv[d];
    float s = 0.f;

    for (int l0 = 0; l0 < LL; l0 += SCH) {
        float dtv[SCH], hsv[SCH], Bv[SCH], Cv[SCH], gv[SCH];
#pragma unroll
        for (int j = 0; j < SCH; j++) {
            int l = l0 + j;
            dtv[j] = g_dt[(size_t)l * DDI + d];
            hsv[j] = __half2float(g_hsh[(size_t)l * DDI + d]);
            Bv[j]  = g_tsbc[l * 160 + 128 + n];
            Cv[j]  = g_tsbc[l * 160 + 144 + n];
            gv[j]  = g_pg[(size_t)l * 8192 + 4096 + d];
        }
#pragma unroll
        for (int j = 0; j < SCH; j++) {
            float a = __expf(Acoef * dtv[j]);
            s = fmaf(a, s, dtv[j] * Bv[j] * hsv[j]);
            float v = s * Cv[j];
            v += __shfl_xor_sync(0xFFFFFFFFu, v, 1);
            v += __shfl_xor_sync(0xFFFFFFFFu, v, 2);
            v += __shfl_xor_sync(0xFFFFFFFFu, v, 4);
            v += __shfl_xor_sync(0xFFFFFFFFu, v, 8);
            if (n == 0) {
                float gvv = gv[j];
                float y = (v + hsv[j] * Dd) * (gvv / (1.f + __expf(-gvv)));
                g_yh[(size_t)(l0 + j) * DDI + d] = __float2half_rn(y);
            }
        }
    }
}

// ---------------- host ----------------
extern "C" void kernel_launch(void* const* d_in, const int* in_sizes, int n_in,
                              void* d_out, int out_size)
{
    const float* x           = (const float*)d_in[0];
    const float* W_in_states = (const float*)d_in[1];
    const float* W_in_gates  = (const float*)d_in[2];
    const float* conv_w      = (const float*)d_in[3];
    const float* conv_b      = (const float*)d_in[4];
    const float* W_dt        = (const float*)d_in[5];
    const float* W_b         = (const float*)d_in[6];
    const float* W_c         = (const float*)d_in[7];
    const float* W_dtproj    = (const float*)d_in[8];
    const float* b_dtproj    = (const float*)d_in[9];
    const float* A_log       = (const float*)d_in[10];
    const float* Dv          = (const float*)d_in[11];
    const float* W_out       = (const float*)d_in[12];
    float* out = (float*)d_out;

    float *pg, *dt, *tsbc;
    __half *hsh, *tsh, *yh, *xh, *w12h, *wouth, *wdtbch, *wdtph;
    cudaGetSymbolAddress((void**)&pg,     g_pg);
    cudaGetSymbolAddress((void**)&dt,     g_dt);
    cudaGetSymbolAddress((void**)&tsbc,   g_tsbc);
    cudaGetSymbolAddress((void**)&hsh,    g_hsh);
    cudaGetSymbolAddress((void**)&tsh,    g_tsh);
    cudaGetSymbolAddress((void**)&yh,     g_yh);
    cudaGetSymbolAddress((void**)&xh,     g_xh);
    cudaGetSymbolAddress((void**)&w12h,   g_w12h);
    cudaGetSymbolAddress((void**)&wouth,  g_wouth);
    cudaGetSymbolAddress((void**)&wdtbch, g_wdtbch);
    cudaGetSymbolAddress((void**)&wdtph,  g_wdtph);

    const int SMEM = NSTAGE * STAGE_BYTES;   // 165888 bytes
    cudaFuncSetAttribute(gemm_mma<0>, cudaFuncAttributeMaxDynamicSharedMemorySize, SMEM);
    cudaFuncSetAttribute(gemm_mma<1>, cudaFuncAttributeMaxDynamicSharedMemorySize, SMEM);
    cudaFuncSetAttribute(gemm_mma<3>, cudaFuncAttributeMaxDynamicSharedMemorySize, SMEM);

    auto cv = [&](const float* src, __half* dst, int n) {
        int n4 = n / 4;
        cvt_half<<<(n4 + 255) / 256, 256>>>((const float4*)src, (uint2*)dst, n4);
    };
    cv(x, xh, LL * HH);
    cv(W_in_states, w12h, DDI * HH);
    cv(W_in_gates,  w12h + (size_t)DDI * HH, DDI * HH);
    cv(W_out, wouth, HH * DDI);
    {
        int total4 = (DDI * RR + RR * DDI + 2 * NSS * DDI) / 4;
        cvt_small<<<(total4 + 255) / 256, 256>>>((const float4*)W_dtproj, (const float4*)W_dt,
                                                 (const float4*)W_b, (const float4*)W_c);
    }

    // G12: pg[L, 8192] = x . [W_in_states; W_in_gates]^T
    gemm_mma<0><<<dim3(2 * DDI / BN, LL / BM), 256, SMEM>>>(xh, w12h, pg, nullptr, LL, 2 * DDI, HH, 2 * DDI);
    // conv + silu -> hsh
    conv_silu_kernel<<<(LL * DDI) / 256, 256>>>(conv_w, conv_b);
    // zero split-K accumulator
    zero_kernel<<<(LL * 160 + 255) / 256, 256>>>(tsbc, LL * 160);
    // G35 (split-K=8, atomic): tsbc[L, 160] = hs . [W_dt; W_b; W_c]^T
    gemm_mma<3><<<dim3(1, LL / BM, 8), 256, SMEM>>>(hsh, wdtbch, tsbc, nullptr, LL, 160, DDI, 160);
    // round ts slice -> half
    round_ts_kernel<<<(LL * RR) / 256, 256>>>();
    // G4: dt[L, DI] = softplus(ts . W_dtproj^T + b)
    gemm_mma<1><<<dim3(DDI / BN, LL / BM), 256, SMEM>>>(tsh, wdtph, dt, b_dtproj, LL, DDI, RR, DDI);
    // scan + gating -> yh (register-blocked)
    scan_kernel<<<(DDI / 2 * 32) / 256, 256>>>(A_log, Dv);
    // zero output, then G6 (split-K=2, atomic): out = y . W_out^T
    zero_kernel<<<(LL * HH + 255) / 256, 256>>>(out, LL * HH);
    gemm_mma<3><<<dim3(HH / BN, LL / BM, 2), 256, SMEM>>>(yh, wouth, out, nullptr, LL, HH, DDI, HH);
}